// round 17
// baseline (speedup 1.0000x reference)
#include <cuda_runtime.h>

// KnnLoss via anisotropic spatial grid, warp-per-query, segmented packed
// sweep, per-query adaptive radius gate:
// B=4, N=8192, C=3, K=16, RADIUS=0.5, L2.
// Only the <=16 nearest in-radius neighbors contribute. A gate G < RADIUS is
// lossless whenever >=16 candidates fall under it (the global 16th-smallest
// is then < G). Per query: G = 0.0649*exp(s^2/3) (targets ~36 expected hits
// from the Gaussian density model cnt(s) = 272*exp(-s^2/2)), clamped at the
// full gate, floored to a key-quantization boundary. If a clamped-gate pass
// collects <16, a rare (~1e-4) second pass rescans at the full radius.
// Grid: y,z at 0.5 (16 cells), x at 0.125 (64 cells); per (z,y) row the
// x-window is the exact circular bound |dx| <= sqrt(gate - rd2) (+slack).
// K1 (fused build, 64 CTAs of 512, all resident => spin-safe): histogram
//   with register rank capture + flow L2 prefetch + per-batch elected scan
//   (3-level: chunk totals parked per-lane => all 32 chunks of pass B are
//   INDEPENDENT, no serial carry chain) + register scatter + batch-local
//   count re-zero (graph-replay clean).
// K2: per query-warp: lanes 0..8 compute the 9 row runs in parallel; shfl
//   scan concatenates them into one packed index space swept in fully packed
//   32-lane iterations (monotone segment cursor). In-gate keys (17-bit
//   quantized d2 | 13-bit idx => unique, tie = lower idx like top_k) are
//   ballot-compacted; top-16 via register tournament; parallel flow norms;
//   last CTA reduces partials.

#define BB 4
#define NN 8192
#define KK 16
#define GY 16
#define GX 64
#define NCELLS (GY * GY * GX)        // 16384
#define TPB 256
#define WPB (TPB / 32)               // 8 queries per CTA
#define CAP 512
#define NPART (NN / WPB)             // 1024 CTAs per batch
#define NCTAS (BB * NPART)           // 4096
#define IMAX 0x7FFFFFFF
#define RGATE 0.2500001f             // keep d2 whose sqrt rounds to <= 0.5

#define HTPB 512                     // build kernel: 512 thr, 64 CTAs
#define HCTAS (BB * NN / HTPB)       // 64 (<= 148 SMs => all resident)
#define CTAS_PER_B (HCTAS / BB)      // 16
#define TPB_PER_B (CTAS_PER_B * HTPB)         // 8192 threads per batch
#define FLOW_LINES ((BB * NN * 3 * 4) / 128)  // 3072 128B lines

__device__ int g_counts[BB * NCELLS];      // zero-init; re-zeroed each run
__device__ int g_offsets[BB * (NCELLS + 1)];
__device__ float4 g_sorted[BB * NN + 64];  // pad: unpredicated sweep loads
__device__ float g_partials[NCTAS];
__device__ int g_bdone[BB];     // per-batch hist tickets; self-reset
__device__ int g_bdone2[BB];    // per-batch exit tickets; self-reset
__device__ int g_scanflag[BB];  // per-batch scan-complete flags; self-reset
__device__ int g_done;          // main-kernel ticket; self-reset

__device__ __forceinline__ int cell_yz(float v) {
    int c = (int)floorf((v + 4.0f) * 2.0f);
    return min(max(c, 0), GY - 1);
}
__device__ __forceinline__ int cell_x(float v) {
    int c = (int)floorf((v + 4.0f) * 8.0f);
    return min(max(c, 0), GX - 1);
}

#define CSWAP(a, b) { int t_ = min(a, b); b = max(a, b); a = t_; }

// ---- K1: fused histogram + scan + scatter ----
__global__ __launch_bounds__(HTPB) void build_kernel(
    const float* __restrict__ pc, const float* __restrict__ flow) {
    __shared__ int wtot[16];
    __shared__ int lastflag;
    const int t = threadIdx.x;
    const int lane = t & 31, w = t >> 5;
    const int gid = blockIdx.x * HTPB + t;
    const int b = blockIdx.x / CTAS_PER_B;  // CTA handles one batch only
    const int tl = gid - b * TPB_PER_B;     // thread index within batch
    const int n = gid & (NN - 1);

    const float* pp = pc + (size_t)b * NN * 3 + 3 * n;
    float px = pp[0], py = pp[1], pz = pp[2];
    int cell = (cell_yz(pz) * GY + cell_yz(py)) * GX + cell_x(px);
    int rank = atomicAdd(&g_counts[b * NCELLS + cell], 1);

    if (gid < FLOW_LINES)
        asm volatile("prefetch.global.L2 [%0];" ::
                     "l"(flow + (size_t)gid * 32));

    __threadfence();
    __syncthreads();
    if (t == 0)
        lastflag = (atomicAdd(&g_bdone[b], 1) == CTAS_PER_B - 1) ? 1 : 0;
    __syncthreads();

    if (lastflag) {
        __threadfence();
        // 3-level scan of 16384 counts: warp w owns cells
        // [w*1024, w*1024+1024) as 32 chunks of 32.
        const int* cnt = g_counts + b * NCELLS;
        int* off = g_offsets + b * (NCELLS + 1);
        const int wbase = w * 1024;

        // Pass A: chunk totals; chunk i's total parked on lane i.
        int chunktot = 0;
#pragma unroll
        for (int i = 0; i < 32; ++i) {
            int v = cnt[wbase + i * 32 + lane];
            int s = v;
#pragma unroll
            for (int o = 16; o > 0; o >>= 1)
                s += __shfl_xor_sync(0xFFFFFFFFu, s, o);
            if (lane == i) chunktot = s;
        }
        // Exclusive scan of the 32 chunk totals (registers only).
        int cpre = chunktot;
#pragma unroll
        for (int o = 1; o < 32; o <<= 1) {
            int u = __shfl_up_sync(0xFFFFFFFFu, cpre, o);
            if (lane >= o) cpre += u;
        }
        int warptot = __shfl_sync(0xFFFFFFFFu, cpre, 31);
        cpre -= chunktot;  // exclusive chunk prefix, lane i => chunk i
        if (lane == 0) wtot[w] = warptot;
        __syncthreads();
        if (w == 0 && lane < 16) {
            int x = wtot[lane];
#pragma unroll
            for (int o = 1; o < 16; o <<= 1) {
                int u = __shfl_up_sync(0x0000FFFFu, x, o);
                if (lane >= o) x += u;
            }
            wtot[lane] = x;
        }
        __syncthreads();
        const int woff = (w > 0) ? wtot[w - 1] : 0;

        // Pass B: all 32 chunks independent (no serial carry).
#pragma unroll
        for (int i = 0; i < 32; ++i) {
            int idx = wbase + i * 32 + lane;
            int v = cnt[idx];
            int s = v;
#pragma unroll
            for (int o = 1; o < 32; o <<= 1) {
                int u = __shfl_up_sync(0xFFFFFFFFu, s, o);
                if (lane >= o) s += u;
            }
            off[idx] = s - v + woff + __shfl_sync(0xFFFFFFFFu, cpre, i);
        }
        __syncthreads();
        if (t == 0) {
            off[NCELLS] = NN;  // grand total is exactly NN
            g_bdone[b] = 0;    // reset hist ticket for next replay
            __threadfence();
            g_scanflag[b] = 1;  // release the batch
        }
    }

    if (t == 0)
        while (*(volatile int*)&g_scanflag[b] == 0) __nanosleep(32);
    __syncthreads();
    __threadfence();

    // Scatter from registers; re-zero ONLY this batch's counts.
    int pos = g_offsets[b * (NCELLS + 1) + cell] + rank;
    g_sorted[b * NN + pos] = make_float4(px, py, pz, __int_as_float(n));
    g_counts[b * NCELLS + tl] = 0;
    g_counts[b * NCELLS + TPB_PER_B + tl] = 0;

    __syncthreads();
    if (t == 0 && atomicAdd(&g_bdone2[b], 1) == CTAS_PER_B - 1) {
        g_scanflag[b] = 0;
        g_bdone2[b] = 0;
    }
}

// ---- K2: main, warp per query; last CTA finalizes ----
__global__ __launch_bounds__(TPB, 8) void knn_loss_kernel(
    const float* __restrict__ flow, float* __restrict__ out) {
    __shared__ int buf[WPB][CAP];
    __shared__ int cseg[WPB][16];  // cumulative segment ends (IMAX pad)
    __shared__ int bseg[WPB][16];  // rebased segment starts
    __shared__ float cpart[WPB];
    __shared__ int lastflag;

    const int b = blockIdx.y;
    const int w = threadIdx.x >> 5;
    const int lane = threadIdx.x & 31;
    const unsigned lt_mask = (1u << lane) - 1u;
    const int sp = blockIdx.x * WPB + w;
    int* __restrict__ bw = buf[w];
    const float4* __restrict__ sb = g_sorted + b * NN;
    const int* __restrict__ ob = g_offsets + b * (NCELLS + 1);
    const float* __restrict__ flb = flow + (size_t)b * NN * 3;

    const float4 me = sb[sp];  // broadcast
    const int qi = __float_as_int(me.w);
    const int cy = cell_yz(me.y), cz = cell_yz(me.z);
    const float fy = fmaf((float)cy, -0.5f, me.y + 4.0f);
    const float fz = fmaf((float)cz, -0.5f, me.z + 4.0f);

    // Adaptive gate: target ~36 expected hits (2.25x margin over K=16;
    // P(<16 | lambda=36) ~ 1e-4, handled by the exact fallback pass).
    // cnt_est(s) = 272*exp(-s^2/2) => G = 0.25*(36/cnt_est)^(2/3)
    //                                   = 0.0649*exp(s^2/3), clamped.
    const float s2q = fmaf(me.x, me.x, fmaf(me.y, me.y, me.z * me.z));
    const float Graw = 0.0649f * __expf(s2q * (1.0f / 3.0f));
    bool fullgate = (Graw >= RGATE);
    // Floor to a key-quantization boundary: gate membership becomes exactly
    // a key comparison (no new error class vs the existing quantizer).
    float gate = fullgate ? RGATE
                          : floorf(Graw * 262144.0f) * (1.0f / 262144.0f);

    int cnt;
    for (;;) {  // pass 1: adaptive gate; pass 2 (rare): full gate
        const float gate2 = gate + 1.0e-7f;
        // Lanes 0..8 compute their row's run [s0, s0+len) in parallel.
        {
            int dz = lane / 3 - 1, dy = lane - (lane / 3) * 3 - 1;
            int z2 = cz + dz, y2 = cy + dy;
            bool okrow = (lane < 9) && ((unsigned)z2 < (unsigned)GY) &&
                         ((unsigned)y2 < (unsigned)GY);
            float dy2 = (dy == 0) ? 0.0f
                                  : ((dy < 0) ? fy * fy
                                              : (0.5f - fy) * (0.5f - fy));
            float dz2 = (dz == 0) ? 0.0f
                                  : ((dz < 0) ? fz * fz
                                              : (0.5f - fz) * (0.5f - fz));
            float rd2 = dy2 + dz2;
            okrow = okrow && (rd2 <= gate2);
            int s0 = 0, len = 0;
            if (okrow) {
                // Exact circular x-window (round-up + slack: clamped
                // monotone cell map provably covers the in-gate disk).
                float ww = __fsqrt_ru(gate2 - rd2) + 4e-6f;
                int xl = cell_x(me.x - ww);
                int xh = cell_x(me.x + ww);
                int base = (z2 * GY + y2) * GX;
                s0 = ob[base + xl];
                len = ob[base + xh + 1] - s0;
            }
            int c = len;  // inclusive scan (lanes >=9 contribute 0)
#pragma unroll
            for (int o = 1; o < 16; o <<= 1) {
                int u = __shfl_up_sync(0xFFFFFFFFu, c, o);
                if (lane >= o) c += u;
            }
            if (lane < 16) {
                cseg[w][lane] = (lane < 9) ? c : IMAX;
                bseg[w][lane] = (lane < 9) ? (s0 - (c - len)) : 0;
            }
        }
        __syncwarp();
        const int L = cseg[w][8];  // total candidates (broadcast LDS)

        // Packed sweep over the concatenated index space, fully 32-wide.
        cnt = 0;  // warp-uniform
        {
            int r = 0;
            int cend = cseg[w][0];
            int kbase = bseg[w][0];
            const int nit = (L + 31) >> 5;
            for (int it = 0; it < nit; ++it) {
                int g = (it << 5) + lane;
                while (g >= cend) {  // monotone cursor, <=9 advances/lane
                    ++r;
                    cend = cseg[w][r];
                    kbase = bseg[w][r];
                }
                int k = kbase + g;  // invalid lanes (g>=L): r=9 => k=g, safe
                float4 p = sb[k];
                float ddx = me.x - p.x;
                float ddy = me.y - p.y;
                float ddz = me.z - p.z;
                float d2 = fmaf(ddx, ddx, fmaf(ddy, ddy, ddz * ddz));
                bool inr = (d2 < gate) & (g < L);
                unsigned mask = __ballot_sync(0xFFFFFFFFu, inr);
                if (inr) {
                    int key = ((int)(d2 * 262144.0f) << 13) |
                              __float_as_int(p.w);
                    int pos = cnt + __popc(mask & lt_mask);
                    if (pos < CAP) bw[pos] = key;
                }
                cnt += __popc(mask);
            }
        }
        cnt = min(cnt, CAP);
        __syncwarp();

        // Gate validity: >=16 hits under a reduced gate => the global top-16
        // are all inside it. Otherwise rescan once at the full radius.
        if (cnt >= KK || fullgate) break;
        gate = RGATE;
        fullgate = true;
    }

    // Phase 2: top-16 selection; winners parked one per lane.
    const int R = min(cnt, KK);
    int selkey = IMAX;
    if (cnt <= KK) {
        selkey = (lane < cnt) ? bw[lane] : IMAX;
    } else if (cnt <= 64) {
        int v0 = (lane < cnt) ? bw[lane] : IMAX;
        int v1 = (lane + 32 < cnt) ? bw[lane + 32] : IMAX;
        CSWAP(v0, v1);
        for (int r = 0; r < R; ++r) {
            int gmin = __reduce_min_sync(0xFFFFFFFFu, v0);
            bool won = (v0 == gmin);  // unique keys => exactly one winner
            v0 = won ? v1 : v0;
            v1 = won ? IMAX : v1;
            if (lane == r) selkey = gmin;
        }
    } else if (cnt <= 128) {
        int v0 = (lane < cnt) ? bw[lane] : IMAX;
        int v1 = (lane + 32 < cnt) ? bw[lane + 32] : IMAX;
        int v2 = (lane + 64 < cnt) ? bw[lane + 64] : IMAX;
        int v3 = (lane + 96 < cnt) ? bw[lane + 96] : IMAX;
        CSWAP(v0, v1); CSWAP(v2, v3); CSWAP(v0, v2); CSWAP(v1, v3);
        CSWAP(v1, v2);
        for (int r = 0; r < R; ++r) {
            int gmin = __reduce_min_sync(0xFFFFFFFFu, v0);
            bool won = (v0 == gmin);
            v0 = won ? v1 : v0;
            v1 = won ? v2 : v1;
            v2 = won ? v3 : v2;
            v3 = won ? IMAX : v3;
            if (lane == r) selkey = gmin;
        }
    } else if (cnt <= 256) {
        int v0 = (lane < cnt) ? bw[lane] : IMAX;
        int v1 = (lane + 32 < cnt) ? bw[lane + 32] : IMAX;
        int v2 = (lane + 64 < cnt) ? bw[lane + 64] : IMAX;
        int v3 = (lane + 96 < cnt) ? bw[lane + 96] : IMAX;
        int v4 = (lane + 128 < cnt) ? bw[lane + 128] : IMAX;
        int v5 = (lane + 160 < cnt) ? bw[lane + 160] : IMAX;
        int v6 = (lane + 192 < cnt) ? bw[lane + 192] : IMAX;
        int v7 = (lane + 224 < cnt) ? bw[lane + 224] : IMAX;
        // Batcher odd-even merge sort for 8.
        CSWAP(v0, v1); CSWAP(v2, v3); CSWAP(v4, v5); CSWAP(v6, v7);
        CSWAP(v0, v2); CSWAP(v1, v3); CSWAP(v4, v6); CSWAP(v5, v7);
        CSWAP(v1, v2); CSWAP(v5, v6);
        CSWAP(v0, v4); CSWAP(v1, v5); CSWAP(v2, v6); CSWAP(v3, v7);
        CSWAP(v2, v4); CSWAP(v3, v5);
        CSWAP(v1, v2); CSWAP(v3, v4); CSWAP(v5, v6);
        for (int r = 0; r < R; ++r) {
            int gmin = __reduce_min_sync(0xFFFFFFFFu, v0);
            bool won = (v0 == gmin);
            v0 = won ? v1 : v0;
            v1 = won ? v2 : v1;
            v2 = won ? v3 : v2;
            v3 = won ? v4 : v3;
            v4 = won ? v5 : v4;
            v5 = won ? v6 : v5;
            v6 = won ? v7 : v6;
            v7 = won ? IMAX : v7;
            if (lane == r) selkey = gmin;
        }
    } else {
        const int P = (cnt + 31) >> 5;
        for (int r = 0; r < R; ++r) {
            int mymin = IMAX, myidx = 0;
            for (int i = 0; i < P; ++i) {
                int k = lane + (i << 5);
                int vv = (k < cnt) ? bw[k] : IMAX;
                if (vv < mymin) { mymin = vv; myidx = k; }
            }
            int gmin = __reduce_min_sync(0xFFFFFFFFu, mymin);
            if (mymin == gmin && gmin != IMAX) bw[myidx] = IMAX;
            if (lane == r) selkey = gmin;
            __syncwarp();
        }
    }

    // Phase 3: selected lanes compute flow norms; warp + CTA reduce.
    float acc = 0.0f;
    if (selkey != IMAX) {
        const int j = selkey & (NN - 1);  // j==qi (self) => exact 0
        float ddx = flb[3 * qi + 0] - flb[3 * j + 0];
        float ddy = flb[3 * qi + 1] - flb[3 * j + 1];
        float ddz = flb[3 * qi + 2] - flb[3 * j + 2];
        acc = __fsqrt_rn(fmaf(ddx, ddx, fmaf(ddy, ddy, ddz * ddz)));
    }
#pragma unroll
    for (int o = 16; o > 0; o >>= 1)
        acc += __shfl_xor_sync(0xFFFFFFFFu, acc, o);
    if (lane == 0) cpart[w] = acc;
    __syncthreads();
    if (threadIdx.x == 0) {
        float s = 0.0f;
#pragma unroll
        for (int i = 0; i < WPB; ++i) s += cpart[i];
        g_partials[b * NPART + blockIdx.x] = s;
        __threadfence();
        int d = atomicAdd(&g_done, 1);
        lastflag = (d == NCTAS - 1) ? 1 : 0;
    }
    __syncthreads();

    // Last CTA: deterministic fixed-order reduction of all partials.
    if (lastflag) {
        __threadfence();
        float s2 = 0.0f;
#pragma unroll
        for (int i = 0; i < NCTAS / TPB; ++i)
            s2 += g_partials[threadIdx.x + i * TPB];
#pragma unroll
        for (int o = 16; o > 0; o >>= 1)
            s2 += __shfl_xor_sync(0xFFFFFFFFu, s2, o);
        if (lane == 0) cpart[w] = s2;
        __syncthreads();
        if (threadIdx.x == 0) {
            float s3 = 0.0f;
#pragma unroll
            for (int i = 0; i < WPB; ++i) s3 += cpart[i];
            out[0] = s3 * (1.0f / (float)((size_t)BB * NN * KK));
            g_done = 0;  // reset for next graph replay
        }
    }
}

extern "C" void kernel_launch(void* const* d_in, const int* in_sizes, int n_in,
                              void* d_out, int out_size) {
    const float* pc = (const float*)d_in[0];
    const float* flow = (const float*)d_in[1];

    build_kernel<<<HCTAS, HTPB>>>(pc, flow);
    dim3 grid(NN / WPB, BB);
    knn_loss_kernel<<<grid, TPB>>>(flow, (float*)d_out);
}